// round 1
// baseline (speedup 1.0000x reference)
#include <cuda_runtime.h>
#include <cuda_bf16.h>
#include <cstdint>

// Problem dims
#define B_   4096
#define S_   10
#define H_   32
#define DH_  64
#define E_   1024
#define HID_ 2048

// GEMM tiling
#define BM 128
#define BN 128
#define BK 16

// Scratch (allocation-free rule: __device__ globals)
__device__ float g_Q[(size_t)B_ * HID_];
__device__ float g_K[(size_t)B_ * HID_];
__device__ float g_vsum[HID_];

// ---------------------------------------------------------------------------
// Fused QKV GEMM: C[m, n] = sum_k emb[t[m]][k] * W[n][k] + bias[n]
// grid = (HID/BN, B/BM, 3); z selects (Wq->g_Q, Wk->g_K, Wv->d_out[0:B*HID))
// ---------------------------------------------------------------------------
__global__ __launch_bounds__(256, 1)
void qkv_gemm_kernel(const int* __restrict__ t, const float* __restrict__ emb,
                     const float* __restrict__ Wq, const float* __restrict__ bq,
                     const float* __restrict__ Wk, const float* __restrict__ bk,
                     const float* __restrict__ Wv, const float* __restrict__ bv,
                     float* __restrict__ outV)
{
    __shared__ float As[BK][BM];
    __shared__ float Bs[BK][BN];
    __shared__ int   rowidx[BM];

    const float* W;
    const float* bias;
    float*       C;
    if (blockIdx.z == 0)      { W = Wq; bias = bq; C = g_Q;  }
    else if (blockIdx.z == 1) { W = Wk; bias = bk; C = g_K;  }
    else                      { W = Wv; bias = bv; C = outV; }

    const int tid = threadIdx.x;
    const int m0  = blockIdx.y * BM;
    const int n0  = blockIdx.x * BN;

    if (tid < BM) rowidx[tid] = t[m0 + tid];
    __syncthreads();

    float acc[8][8];
#pragma unroll
    for (int i = 0; i < 8; i++)
#pragma unroll
        for (int j = 0; j < 8; j++) acc[i][j] = 0.0f;

    const int tm = (tid >> 4) << 3;    // 0..120 step 8
    const int tn = (tid & 15) << 3;    // 0..120 step 8

    const int lr = tid >> 2;           // 0..63
    const int lc = (tid & 3) << 2;     // 0,4,8,12

    for (int k0 = 0; k0 < E_; k0 += BK) {
#pragma unroll
        for (int i = 0; i < 2; i++) {
            const int r = lr + i * 64;
            const float4 av = *(const float4*)(emb + (size_t)rowidx[r] * E_ + k0 + lc);
            As[lc + 0][r] = av.x;
            As[lc + 1][r] = av.y;
            As[lc + 2][r] = av.z;
            As[lc + 3][r] = av.w;
            const float4 wv = *(const float4*)(W + (size_t)(n0 + r) * E_ + k0 + lc);
            Bs[lc + 0][r] = wv.x;
            Bs[lc + 1][r] = wv.y;
            Bs[lc + 2][r] = wv.z;
            Bs[lc + 3][r] = wv.w;
        }
        __syncthreads();

#pragma unroll
        for (int kk = 0; kk < BK; kk++) {
            const float4 a0 = *(const float4*)&As[kk][tm];
            const float4 a1 = *(const float4*)&As[kk][tm + 4];
            const float4 b0 = *(const float4*)&Bs[kk][tn];
            const float4 b1 = *(const float4*)&Bs[kk][tn + 4];
            const float a[8] = {a0.x, a0.y, a0.z, a0.w, a1.x, a1.y, a1.z, a1.w};
            const float b[8] = {b0.x, b0.y, b0.z, b0.w, b1.x, b1.y, b1.z, b1.w};
#pragma unroll
            for (int i = 0; i < 8; i++)
#pragma unroll
                for (int j = 0; j < 8; j++) acc[i][j] += a[i] * b[j];
        }
        __syncthreads();
    }

#pragma unroll
    for (int i = 0; i < 8; i++) {
        const int row = m0 + tm + i;
#pragma unroll
        for (int j = 0; j < 8; j += 4) {
            const int col = n0 + tn + j;
            float4 o;
            o.x = acc[i][j + 0] + bias[col + 0];
            o.y = acc[i][j + 1] + bias[col + 1];
            o.z = acc[i][j + 2] + bias[col + 2];
            o.w = acc[i][j + 3] + bias[col + 3];
            *(float4*)(C + (size_t)row * HID_ + col) = o;
        }
    }
}

// ---------------------------------------------------------------------------
// Vsum[i] = sum_{s<10} V[s][i]   (V == target_vector == d_out first half)
// ---------------------------------------------------------------------------
__global__ void vsum_kernel(const float* __restrict__ V)
{
    const int i = blockIdx.x * blockDim.x + threadIdx.x;
    if (i < HID_) {
        float s = 0.0f;
#pragma unroll
        for (int r = 0; r < S_; r++) s += V[(size_t)r * HID_ + i];
        g_vsum[i] = s;
    }
}

// ---------------------------------------------------------------------------
// Per-batch attention:
//   scores[h,g] = Q[b,h,:].K[b,g,:] / 8 ; attn = softmax_g ;
//   ctx[b, h*64+d] = sum_g attn[h,g] * Vsum[g*64+d]
// one block per batch element, 256 threads
// ---------------------------------------------------------------------------
__global__ __launch_bounds__(256, 1)
void attn_kernel(float* __restrict__ ctx)
{
    __shared__ float sQ[H_][DH_ + 4];
    __shared__ float sK[H_][DH_ + 4];
    __shared__ float sV[H_][DH_ + 4];
    __shared__ float sS[H_][H_ + 1];

    const int b   = blockIdx.x;
    const int tid = threadIdx.x;
    const float* Qb = g_Q + (size_t)b * HID_;
    const float* Kb = g_K + (size_t)b * HID_;

    for (int i = tid; i < HID_; i += 256) {
        const int g = i >> 6, j = i & 63;
        sQ[g][j] = Qb[i];
        sK[g][j] = Kb[i];
        sV[g][j] = g_vsum[i];
    }
    __syncthreads();

    // scores (1024 dots of length 64; 4 per thread)
    for (int e = tid; e < H_ * H_; e += 256) {
        const int h = e >> 5, g = e & 31;
        float s = 0.0f;
#pragma unroll
        for (int j = 0; j < DH_; j++) s += sQ[h][j] * sK[g][j];
        sS[h][g] = s * 0.125f;   // 1/sqrt(64)
    }
    __syncthreads();

    // softmax per row (threads 0..31)
    if (tid < H_) {
        float m = -1e30f;
#pragma unroll
        for (int g = 0; g < H_; g++) m = fmaxf(m, sS[tid][g]);
        float sum = 0.0f;
#pragma unroll
        for (int g = 0; g < H_; g++) {
            const float e = expf(sS[tid][g] - m);
            sS[tid][g] = e;
            sum += e;
        }
        const float inv = 1.0f / sum;
#pragma unroll
        for (int g = 0; g < H_; g++) sS[tid][g] *= inv;
    }
    __syncthreads();

    // ctx = attn @ Vsum ; thread -> (h, 8 consecutive d)
    const int h  = tid >> 3;
    const int d0 = (tid & 7) << 3;
    float o[8];
#pragma unroll
    for (int j = 0; j < 8; j++) o[j] = 0.0f;
#pragma unroll
    for (int g = 0; g < H_; g++) {
        const float a = sS[h][g];
#pragma unroll
        for (int j = 0; j < 8; j++) o[j] += a * sV[g][d0 + j];
    }
    float* out = ctx + (size_t)b * HID_ + h * DH_ + d0;
    float4 o0 = {o[0], o[1], o[2], o[3]};
    float4 o1 = {o[4], o[5], o[6], o[7]};
    *(float4*)(out + 0) = o0;
    *(float4*)(out + 4) = o1;
}

// ---------------------------------------------------------------------------
extern "C" void kernel_launch(void* const* d_in, const int* in_sizes, int n_in,
                              void* d_out, int out_size)
{
    const int*   t   = (const int*)d_in[0];
    // d_in[1] = c : computed-but-unused in reference
    const float* emb = (const float*)d_in[2];
    const float* Wq  = (const float*)d_in[3];
    const float* bq  = (const float*)d_in[4];
    const float* Wk  = (const float*)d_in[5];
    const float* bk  = (const float*)d_in[6];
    const float* Wv  = (const float*)d_in[7];
    const float* bv  = (const float*)d_in[8];

    float* out = (float*)d_out;
    float* tgt = out;                       // target_vector [B, HID]
    float* ctx = out + (size_t)B_ * HID_;   // context_vector [B, HID]

    dim3 grid(HID_ / BN, B_ / BM, 3);
    qkv_gemm_kernel<<<grid, 256>>>(t, emb, Wq, bq, Wk, bk, Wv, bv, tgt);
    vsum_kernel<<<8, 256>>>(tgt);
    attn_kernel<<<B_, 256>>>(ctx);
}

// round 3
// speedup vs baseline: 2.1290x; 2.1290x over previous
#include <cuda_runtime.h>
#include <cuda_bf16.h>
#include <cstdint>

#define B_   4096
#define S_   10
#define H_   32
#define DH_  64
#define E_   1024
#define HID_ 2048

// GEMM tiling
#define BM 128
#define BN 128
#define BKE 32               // bf16 elements per k-chunk
#define NSTG 4
#define NCHUNK 96            // K' = 3*1024 / 32
#define STAGE_BYTES 16384    // (128 rows * 64 B) * 2 operands
#define SMEM_TOTAL (1024 + NSTG * STAGE_BYTES)

// ---------------------------------------------------------------------------
// Scratch (__device__ globals; allocation-free rule)
// ---------------------------------------------------------------------------
__device__ float g_Q[(size_t)B_ * HID_];
__device__ float g_K[(size_t)B_ * HID_];
__device__ float g_vsum[HID_];
__device__ __nv_bfloat16 g_Ahi[(size_t)B_ * E_];
__device__ __nv_bfloat16 g_Alo[(size_t)B_ * E_];
__device__ __nv_bfloat16 g_Whi[3][(size_t)HID_ * E_];
__device__ __nv_bfloat16 g_Wlo[3][(size_t)HID_ * E_];

// ---------------------------------------------------------------------------
// PTX helpers (non-'a' baseline ISA only: cp.async / ldmatrix / mma.sync)
// ---------------------------------------------------------------------------
__device__ __forceinline__ uint32_t s2u(const void* p) {
    return (uint32_t)__cvta_generic_to_shared(p);
}
__device__ __forceinline__ void cp16(uint32_t dst, const void* src) {
    asm volatile("cp.async.cg.shared.global [%0], [%1], 16;"
                 :: "r"(dst), "l"(__cvta_generic_to_global(src)));
}
#define CP_COMMIT() asm volatile("cp.async.commit_group;" ::: "memory")
#define CP_WAIT2()  asm volatile("cp.async.wait_group 2;" ::: "memory")

__device__ __forceinline__ void ldm4(uint32_t* r, uint32_t addr) {
    asm volatile("ldmatrix.sync.aligned.m8n8.x4.shared.b16 {%0,%1,%2,%3}, [%4];"
                 : "=r"(r[0]), "=r"(r[1]), "=r"(r[2]), "=r"(r[3]) : "r"(addr));
}
__device__ __forceinline__ void mma16816(float* d, const uint32_t* a,
                                         uint32_t b0, uint32_t b1) {
    asm volatile("mma.sync.aligned.m16n8k16.row.col.f32.bf16.bf16.f32 "
                 "{%0,%1,%2,%3}, {%4,%5,%6,%7}, {%8,%9}, {%0,%1,%2,%3};"
                 : "+f"(d[0]), "+f"(d[1]), "+f"(d[2]), "+f"(d[3])
                 : "r"(a[0]), "r"(a[1]), "r"(a[2]), "r"(a[3]),
                   "r"(b0), "r"(b1));
}

// ---------------------------------------------------------------------------
// Prep: gather emb[t] and split fp32 -> (bf16 hi, bf16 lo) for A and Wq/Wk/Wv
// ---------------------------------------------------------------------------
__global__ __launch_bounds__(256)
void convert_kernel(const int* __restrict__ t, const float* __restrict__ emb,
                    const float* __restrict__ Wq, const float* __restrict__ Wk,
                    const float* __restrict__ Wv)
{
    const int gid = blockIdx.x * 256 + threadIdx.x;
    const int A4 = B_ * E_ / 4;
    const int W4 = HID_ * E_ / 4;
    const float* src;
    __nv_bfloat16 *dhi, *dlo;
    size_t off;
    if (gid < A4) {
        const int b  = gid >> 8;
        const int k4 = gid & 255;
        src = emb + (size_t)t[b] * E_ + (size_t)k4 * 4;
        off = (size_t)b * E_ + (size_t)k4 * 4;
        dhi = g_Ahi; dlo = g_Alo;
    } else {
        const int j = gid - A4;
        const int w = j / W4;
        const int r = j - w * W4;
        src = (w == 0 ? Wq : (w == 1 ? Wk : Wv)) + (size_t)r * 4;
        off = (size_t)r * 4;
        dhi = g_Whi[w]; dlo = g_Wlo[w];
    }
    const float4 v = *(const float4*)src;
    __nv_bfloat16 h0 = __float2bfloat16_rn(v.x);
    __nv_bfloat16 h1 = __float2bfloat16_rn(v.y);
    __nv_bfloat16 h2 = __float2bfloat16_rn(v.z);
    __nv_bfloat16 h3 = __float2bfloat16_rn(v.w);
    __nv_bfloat16 l0 = __float2bfloat16_rn(v.x - __bfloat162float(h0));
    __nv_bfloat16 l1 = __float2bfloat16_rn(v.y - __bfloat162float(h1));
    __nv_bfloat16 l2 = __float2bfloat16_rn(v.z - __bfloat162float(h2));
    __nv_bfloat16 l3 = __float2bfloat16_rn(v.w - __bfloat162float(h3));
    *(__nv_bfloat162*)(dhi + off)     = __nv_bfloat162(h0, h1);
    *(__nv_bfloat162*)(dhi + off + 2) = __nv_bfloat162(h2, h3);
    *(__nv_bfloat162*)(dlo + off)     = __nv_bfloat162(l0, l1);
    *(__nv_bfloat162*)(dlo + off + 2) = __nv_bfloat162(l2, l3);
}

// ---------------------------------------------------------------------------
// HMMA GEMM: C[m,n] = sum_k A[m,k]*W[n,k] + bias[n], split via K' = 3K:
//   k' in [0,1024):     A_hi . W_hi
//   k' in [1024,2048):  A_hi . W_lo
//   k' in [2048,3072):  A_lo . W_hi
// CTA 128x128, 8 warps (2x4), warp tile 64x32, mma.sync m16n8k16 bf16,
// 4-stage cp.async pipeline, XOR-swizzled 64B smem rows.
// ---------------------------------------------------------------------------
__global__ __launch_bounds__(256, 1)
void qkv_mma_kernel(const float* __restrict__ bq, const float* __restrict__ bk,
                    const float* __restrict__ bv, float* __restrict__ outT)
{
    extern __shared__ __align__(128) char smem[];
    const int tid  = threadIdx.x;
    const int wid  = tid >> 5;
    const int lane = tid & 31;
    const int z  = blockIdx.z;
    const int m0 = blockIdx.y * BM;
    const int n0 = blockIdx.x * BN;

    const __nv_bfloat16* Whi = g_Whi[z];
    const __nv_bfloat16* Wlo = g_Wlo[z];
    float* C = (z == 0) ? g_Q : (z == 1) ? g_K : outT;
    const float* bias = (z == 0) ? bq : (z == 1) ? bk : bv;

    const uint32_t sb = s2u(smem);
    float* sBias = (float*)smem;
    if (tid < BN) sBias[tid] = bias[n0 + tid];

    float acc[4][4][4];
#pragma unroll
    for (int i = 0; i < 4; i++)
#pragma unroll
        for (int j = 0; j < 4; j++)
#pragma unroll
            for (int k = 0; k < 4; k++) acc[i][j][k] = 0.0f;

    auto load_chunk = [&](int s) {
        const int ph = s >> 5;
        const int k0 = (s & 31) * BKE;
        const __nv_bfloat16* Asrc = (ph == 2) ? g_Alo : g_Ahi;
        const __nv_bfloat16* Bsrc = (ph == 1) ? Wlo : Whi;
        const uint32_t ab = sb + 1024 + (s & 3) * STAGE_BYTES;
        const uint32_t bb = ab + 8192;
#pragma unroll
        for (int i = 0; i < 2; i++) {
            const int idx = tid + i * 256;
            const int row = idx >> 2, kg = idx & 3;
            const uint32_t so = (uint32_t)(row * 64) +
                                (uint32_t)((kg ^ ((row >> 1) & 3)) << 4);
            cp16(ab + so, Asrc + (size_t)(m0 + row) * E_ + k0 + kg * 8);
            cp16(bb + so, Bsrc + (size_t)(n0 + row) * E_ + k0 + kg * 8);
        }
        CP_COMMIT();
    };

    load_chunk(0);
    load_chunk(1);
    load_chunk(2);

    const int m_base = (wid >> 2) * 64;   // 0 or 64
    const int n_base = (wid & 3) * 32;    // 0,32,64,96
    const int r    = lane & 15;
    const int half = lane >> 4;

    for (int c = 0; c < NCHUNK; c++) {
        CP_WAIT2();
        __syncthreads();
        if (c + 3 < NCHUNK) load_chunk(c + 3); else CP_COMMIT();

        const uint32_t aBase = sb + 1024 + (c & 3) * STAGE_BYTES;
        const uint32_t bBase = aBase + 8192;
#pragma unroll
        for (int kk = 0; kk < 2; kk++) {          // two k16 steps per chunk
            const int slot = kk * 2 + half;       // 16B slot within 64B row
            uint32_t Af[4][4], Bf[2][4];
#pragma unroll
            for (int mb = 0; mb < 4; mb++) {
                const int row = m_base + mb * 16 + r;
                const uint32_t addr = aBase + (uint32_t)(row * 64) +
                    (uint32_t)((slot ^ ((row >> 1) & 3)) << 4);
                ldm4(Af[mb], addr);
            }
#pragma unroll
            for (int nb2 = 0; nb2 < 2; nb2++) {
                const int row = n_base + nb2 * 16 + r;
                const uint32_t addr = bBase + (uint32_t)(row * 64) +
                    (uint32_t)((slot ^ ((row >> 1) & 3)) << 4);
                ldm4(Bf[nb2], addr);
            }
#pragma unroll
            for (int mb = 0; mb < 4; mb++)
#pragma unroll
                for (int nb = 0; nb < 4; nb++)
                    mma16816(acc[mb][nb], Af[mb],
                             Bf[nb >> 1][nb & 1], Bf[nb >> 1][(nb & 1) + 2]);
        }
    }
    __syncthreads();

    // epilogue: bias add + store (thread holds cols 2*tig,2*tig+1 at rows g,g+8)
    const int g   = lane >> 2;
    const int tig = lane & 3;
#pragma unroll
    for (int mb = 0; mb < 4; mb++) {
        const int mrow = m0 + m_base + mb * 16 + g;
#pragma unroll
        for (int nb = 0; nb < 4; nb++) {
            const int col = n_base + nb * 8 + 2 * tig;
            const float b0 = sBias[col], b1 = sBias[col + 1];
            float* d0 = C + (size_t)mrow * HID_ + n0 + col;
            float* d1 = d0 + 8 * HID_;
            *(float2*)d0 = float2{acc[mb][nb][0] + b0, acc[mb][nb][1] + b1};
            *(float2*)d1 = float2{acc[mb][nb][2] + b0, acc[mb][nb][3] + b1};
        }
    }
}

// ---------------------------------------------------------------------------
// Vsum[i] = sum_{s<10} V[s][i]
// ---------------------------------------------------------------------------
__global__ void vsum_kernel(const float* __restrict__ V)
{
    const int i = blockIdx.x * blockDim.x + threadIdx.x;
    if (i < HID_) {
        float s = 0.0f;
#pragma unroll
        for (int r = 0; r < S_; r++) s += V[(size_t)r * HID_ + i];
        g_vsum[i] = s;
    }
}

// ---------------------------------------------------------------------------
// Per-batch attention (32x32 scores, softmax, attn @ Vsum)
// ---------------------------------------------------------------------------
__global__ __launch_bounds__(256, 1)
void attn_kernel(float* __restrict__ ctx)
{
    __shared__ __align__(16) float sQ[H_][DH_ + 4];
    __shared__ __align__(16) float sK[H_][DH_ + 4];
    __shared__ __align__(16) float sV[H_][DH_ + 4];
    __shared__ float sS[H_][H_ + 1];

    const int b   = blockIdx.x;
    const int tid = threadIdx.x;
    const float* Qb = g_Q + (size_t)b * HID_;
    const float* Kb = g_K + (size_t)b * HID_;

    for (int i = tid; i < HID_; i += 256) {
        const int g = i >> 6, j = i & 63;
        sQ[g][j] = Qb[i];
        sK[g][j] = Kb[i];
        sV[g][j] = g_vsum[i];
    }
    __syncthreads();

    for (int e = tid; e < H_ * H_; e += 256) {
        const int h = e >> 5, g = e & 31;
        const float4* q4 = (const float4*)&sQ[h][0];
        const float4* k4 = (const float4*)&sK[g][0];
        float s = 0.0f;
#pragma unroll
        for (int j = 0; j < 16; j++) {
            const float4 a = q4[j], bb = k4[j];
            s += a.x * bb.x + a.y * bb.y + a.z * bb.z + a.w * bb.w;
        }
        sS[h][g] = s * 0.125f;
    }
    __syncthreads();

    if (tid < H_) {
        float m = -1e30f;
#pragma unroll
        for (int g = 0; g < H_; g++) m = fmaxf(m, sS[tid][g]);
        float sum = 0.0f;
#pragma unroll
        for (int g = 0; g < H_; g++) {
            const float e = __expf(sS[tid][g] - m);
            sS[tid][g] = e;
            sum += e;
        }
        const float inv = 1.0f / sum;
#pragma unroll
        for (int g = 0; g < H_; g++) sS[tid][g] *= inv;
    }
    __syncthreads();

    const int h  = tid >> 3;
    const int d0 = (tid & 7) << 3;
    float o[8];
#pragma unroll
    for (int j = 0; j < 8; j++) o[j] = 0.0f;
#pragma unroll
    for (int g = 0; g < H_; g++) {
        const float a = sS[h][g];
#pragma unroll
        for (int j = 0; j < 8; j++) o[j] += a * sV[g][d0 + j];
    }
    float* out = ctx + (size_t)b * HID_ + h * DH_ + d0;
    *(float4*)(out + 0) = float4{o[0], o[1], o[2], o[3]};
    *(float4*)(out + 4) = float4{o[4], o[5], o[6], o[7]};
}

// ---------------------------------------------------------------------------
extern "C" void kernel_launch(void* const* d_in, const int* in_sizes, int n_in,
                              void* d_out, int out_size)
{
    (void)in_sizes; (void)n_in; (void)out_size;
    const int*   t   = (const int*)d_in[0];
    const float* emb = (const float*)d_in[2];
    const float* Wq  = (const float*)d_in[3];
    const float* bq  = (const float*)d_in[4];
    const float* Wk  = (const float*)d_in[5];
    const float* bk  = (const float*)d_in[6];
    const float* Wv  = (const float*)d_in[7];
    const float* bv  = (const float*)d_in[8];

    float* out = (float*)d_out;
    float* tgt = out;                       // target_vector [B, HID]
    float* ctx = out + (size_t)B_ * HID_;   // context_vector [B, HID]

    static bool attr_set = false;
    if (!attr_set) {
        cudaFuncSetAttribute(qkv_mma_kernel,
                             cudaFuncAttributeMaxDynamicSharedMemorySize, SMEM_TOTAL);
        attr_set = true;
    }

    const int total4 = (B_ * E_ + 3 * HID_ * E_) / 4;
    convert_kernel<<<total4 / 256, 256>>>(t, emb, Wq, Wk, Wv);

    dim3 grid(HID_ / BN, B_ / BM, 3);
    qkv_mma_kernel<<<grid, 256, SMEM_TOTAL>>>(bq, bk, bv, tgt);

    vsum_kernel<<<8, 256>>>(tgt);
    attn_kernel<<<B_, 256>>>(ctx);
}

// round 4
// speedup vs baseline: 2.6403x; 1.2402x over previous
#include <cuda_runtime.h>
#include <cuda_bf16.h>
#include <cstdint>

#define B_   4096
#define S_   10
#define H_   32
#define DH_  64
#define E_   1024
#define HID_ 2048

// GEMM tiling
#define BM 128
#define BN 128
#define BKE 32
#define NCHUNK 96            // K' = 3*1024 / 32
#define STAGE_BYTES 16384
#define SMEM_TOTAL (1024 + 4 * STAGE_BYTES)

// ---------------------------------------------------------------------------
// Scratch (__device__ globals)
// ---------------------------------------------------------------------------
__device__ __nv_bfloat16 g_Qh[(size_t)B_ * HID_];
__device__ __nv_bfloat16 g_Kh[(size_t)B_ * HID_];
__device__ __nv_bfloat16 g_VTh[DH_ * H_];   // Vsum^T [d][g], hi
__device__ __nv_bfloat16 g_VTl[DH_ * H_];   // Vsum^T [d][g], lo
__device__ __nv_bfloat16 g_Ahi[(size_t)B_ * E_];
__device__ __nv_bfloat16 g_Alo[(size_t)B_ * E_];
__device__ __nv_bfloat16 g_Whi[3][(size_t)HID_ * E_];
__device__ __nv_bfloat16 g_Wlo[3][(size_t)HID_ * E_];

// ---------------------------------------------------------------------------
// PTX helpers
// ---------------------------------------------------------------------------
__device__ __forceinline__ uint32_t s2u(const void* p) {
    return (uint32_t)__cvta_generic_to_shared(p);
}
__device__ __forceinline__ void cp16(uint32_t dst, const void* src) {
    asm volatile("cp.async.cg.shared.global [%0], [%1], 16;"
                 :: "r"(dst), "l"(__cvta_generic_to_global(src)));
}
#define CP_COMMIT() asm volatile("cp.async.commit_group;" ::: "memory")
#define CP_WAIT2()  asm volatile("cp.async.wait_group 2;" ::: "memory")

__device__ __forceinline__ void ldm4(uint32_t* r, uint32_t addr) {
    asm volatile("ldmatrix.sync.aligned.m8n8.x4.shared.b16 {%0,%1,%2,%3}, [%4];"
                 : "=r"(r[0]), "=r"(r[1]), "=r"(r[2]), "=r"(r[3]) : "r"(addr));
}
__device__ __forceinline__ void mma16816(float* d, const uint32_t* a,
                                         uint32_t b0, uint32_t b1) {
    asm volatile("mma.sync.aligned.m16n8k16.row.col.f32.bf16.bf16.f32 "
                 "{%0,%1,%2,%3}, {%4,%5,%6,%7}, {%8,%9}, {%0,%1,%2,%3};"
                 : "+f"(d[0]), "+f"(d[1]), "+f"(d[2]), "+f"(d[3])
                 : "r"(a[0]), "r"(a[1]), "r"(a[2]), "r"(a[3]),
                   "r"(b0), "r"(b1));
}
__device__ __forceinline__ uint32_t packbf2(float x, float y) {
    __nv_bfloat162 v(__float2bfloat16_rn(x), __float2bfloat16_rn(y));
    return *(uint32_t*)&v;
}

// ---------------------------------------------------------------------------
// Prep: gather emb[t], split fp32 -> (bf16 hi, bf16 lo) for A and Wq/Wk/Wv
// ---------------------------------------------------------------------------
__global__ __launch_bounds__(256)
void convert_kernel(const int* __restrict__ t, const float* __restrict__ emb,
                    const float* __restrict__ Wq, const float* __restrict__ Wk,
                    const float* __restrict__ Wv)
{
    const int gid = blockIdx.x * 256 + threadIdx.x;
    const int A4 = B_ * E_ / 4;
    const int W4 = HID_ * E_ / 4;
    const float* src;
    __nv_bfloat16 *dhi, *dlo;
    size_t off;
    if (gid < A4) {
        const int b  = gid >> 8;
        const int k4 = gid & 255;
        src = emb + (size_t)t[b] * E_ + (size_t)k4 * 4;
        off = (size_t)b * E_ + (size_t)k4 * 4;
        dhi = g_Ahi; dlo = g_Alo;
    } else {
        const int j = gid - A4;
        const int w = j / W4;
        const int r = j - w * W4;
        src = (w == 0 ? Wq : (w == 1 ? Wk : Wv)) + (size_t)r * 4;
        off = (size_t)r * 4;
        dhi = g_Whi[w]; dlo = g_Wlo[w];
    }
    const float4 v = *(const float4*)src;
    __nv_bfloat16 h0 = __float2bfloat16_rn(v.x);
    __nv_bfloat16 h1 = __float2bfloat16_rn(v.y);
    __nv_bfloat16 h2 = __float2bfloat16_rn(v.z);
    __nv_bfloat16 h3 = __float2bfloat16_rn(v.w);
    __nv_bfloat16 l0 = __float2bfloat16_rn(v.x - __bfloat162float(h0));
    __nv_bfloat16 l1 = __float2bfloat16_rn(v.y - __bfloat162float(h1));
    __nv_bfloat16 l2 = __float2bfloat16_rn(v.z - __bfloat162float(h2));
    __nv_bfloat16 l3 = __float2bfloat16_rn(v.w - __bfloat162float(h3));
    *(__nv_bfloat162*)(dhi + off)     = __nv_bfloat162(h0, h1);
    *(__nv_bfloat162*)(dhi + off + 2) = __nv_bfloat162(h2, h3);
    *(__nv_bfloat162*)(dlo + off)     = __nv_bfloat162(l0, l1);
    *(__nv_bfloat162*)(dlo + off + 2) = __nv_bfloat162(l2, l3);
}

// ---------------------------------------------------------------------------
// HMMA GEMM (K' = 3K split). z=0 -> g_Qh (bf16), z=1 -> g_Kh (bf16),
// z=2 -> outT (fp32, target_vector).
// ---------------------------------------------------------------------------
__global__ __launch_bounds__(256, 1)
void qkv_mma_kernel(const float* __restrict__ bq, const float* __restrict__ bk,
                    const float* __restrict__ bv, float* __restrict__ outT)
{
    extern __shared__ __align__(128) char smem[];
    const int tid  = threadIdx.x;
    const int wid  = tid >> 5;
    const int lane = tid & 31;
    const int z  = blockIdx.z;
    const int m0 = blockIdx.y * BM;
    const int n0 = blockIdx.x * BN;

    const __nv_bfloat16* Whi = g_Whi[z];
    const __nv_bfloat16* Wlo = g_Wlo[z];
    const float* bias = (z == 0) ? bq : (z == 1) ? bk : bv;

    const uint32_t sb = s2u(smem);
    float* sBias = (float*)smem;
    if (tid < BN) sBias[tid] = bias[n0 + tid];

    float acc[4][4][4];
#pragma unroll
    for (int i = 0; i < 4; i++)
#pragma unroll
        for (int j = 0; j < 4; j++)
#pragma unroll
            for (int k = 0; k < 4; k++) acc[i][j][k] = 0.0f;

    auto load_chunk = [&](int s) {
        const int ph = s >> 5;
        const int k0 = (s & 31) * BKE;
        const __nv_bfloat16* Asrc = (ph == 2) ? g_Alo : g_Ahi;
        const __nv_bfloat16* Bsrc = (ph == 1) ? Wlo : Whi;
        const uint32_t ab = sb + 1024 + (s & 3) * STAGE_BYTES;
        const uint32_t bb = ab + 8192;
#pragma unroll
        for (int i = 0; i < 2; i++) {
            const int idx = tid + i * 256;
            const int row = idx >> 2, kg = idx & 3;
            const uint32_t so = (uint32_t)(row * 64) +
                                (uint32_t)((kg ^ ((row >> 1) & 3)) << 4);
            cp16(ab + so, Asrc + (size_t)(m0 + row) * E_ + k0 + kg * 8);
            cp16(bb + so, Bsrc + (size_t)(n0 + row) * E_ + k0 + kg * 8);
        }
        CP_COMMIT();
    };

    load_chunk(0);
    load_chunk(1);
    load_chunk(2);

    const int m_base = (wid >> 2) * 64;
    const int n_base = (wid & 3) * 32;
    const int r    = lane & 15;
    const int half = lane >> 4;

    for (int c = 0; c < NCHUNK; c++) {
        CP_WAIT2();
        __syncthreads();
        if (c + 3 < NCHUNK) load_chunk(c + 3); else CP_COMMIT();

        const uint32_t aBase = sb + 1024 + (c & 3) * STAGE_BYTES;
        const uint32_t bBase = aBase + 8192;
#pragma unroll
        for (int kk = 0; kk < 2; kk++) {
            const int slot = kk * 2 + half;
            uint32_t Af[4][4], Bf[2][4];
#pragma unroll
            for (int mb = 0; mb < 4; mb++) {
                const int row = m_base + mb * 16 + r;
                const uint32_t addr = aBase + (uint32_t)(row * 64) +
                    (uint32_t)((slot ^ ((row >> 1) & 3)) << 4);
                ldm4(Af[mb], addr);
            }
#pragma unroll
            for (int nb2 = 0; nb2 < 2; nb2++) {
                const int row = n_base + nb2 * 16 + r;
                const uint32_t addr = bBase + (uint32_t)(row * 64) +
                    (uint32_t)((slot ^ ((row >> 1) & 3)) << 4);
                ldm4(Bf[nb2], addr);
            }
#pragma unroll
            for (int mb = 0; mb < 4; mb++)
#pragma unroll
                for (int nb = 0; nb < 4; nb++)
                    mma16816(acc[mb][nb], Af[mb],
                             Bf[nb >> 1][nb & 1], Bf[nb >> 1][(nb & 1) + 2]);
        }
    }
    __syncthreads();

    const int g   = lane >> 2;
    const int tig = lane & 3;
    if (z == 2) {
#pragma unroll
        for (int mb = 0; mb < 4; mb++) {
            const int mrow = m0 + m_base + mb * 16 + g;
#pragma unroll
            for (int nb = 0; nb < 4; nb++) {
                const int col = n_base + nb * 8 + 2 * tig;
                const float b0 = sBias[col], b1 = sBias[col + 1];
                float* d0 = outT + (size_t)mrow * HID_ + n0 + col;
                float* d1 = d0 + 8 * HID_;
                *(float2*)d0 = float2{acc[mb][nb][0] + b0, acc[mb][nb][1] + b1};
                *(float2*)d1 = float2{acc[mb][nb][2] + b0, acc[mb][nb][3] + b1};
            }
        }
    } else {
        __nv_bfloat16* Ch = (z == 0) ? g_Qh : g_Kh;
#pragma unroll
        for (int mb = 0; mb < 4; mb++) {
            const int mrow = m0 + m_base + mb * 16 + g;
#pragma unroll
            for (int nb = 0; nb < 4; nb++) {
                const int col = n_base + nb * 8 + 2 * tig;
                const float b0 = sBias[col], b1 = sBias[col + 1];
                uint32_t p0 = packbf2(acc[mb][nb][0] + b0, acc[mb][nb][1] + b1);
                uint32_t p1 = packbf2(acc[mb][nb][2] + b0, acc[mb][nb][3] + b1);
                *(uint32_t*)(Ch + (size_t)mrow * HID_ + n0 + col) = p0;
                *(uint32_t*)(Ch + (size_t)(mrow + 8) * HID_ + n0 + col) = p1;
            }
        }
    }
}

// ---------------------------------------------------------------------------
// Vsum^T: VT[d][g] = sum_{s<10} tgt[s][g*64+d], split hi/lo bf16
// ---------------------------------------------------------------------------
__global__ void vsum_kernel(const float* __restrict__ tgt)
{
    const int i = blockIdx.x * blockDim.x + threadIdx.x;  // 2048 threads
    if (i < HID_) {
        float s = 0.0f;
#pragma unroll
        for (int r = 0; r < S_; r++) s += tgt[(size_t)r * HID_ + i];
        const int g = i >> 6, d = i & 63;
        const __nv_bfloat16 hi = __float2bfloat16_rn(s);
        g_VTh[d * H_ + g] = hi;
        g_VTl[d * H_ + g] = __float2bfloat16_rn(s - __bfloat162float(hi));
    }
}

// ---------------------------------------------------------------------------
// Tensor-core attention: one warp per batch element.
// scores = Q K^T / 8 (mma, fp32 acc), softmax in-fragment (quad shuffles),
// ctx = P @ Vsum via 3-term hi/lo bf16 split (Phi*Vh + Phi*Vl + Plo*Vh).
// ---------------------------------------------------------------------------
__global__ __launch_bounds__(256, 1)
void attn_mma_kernel(float* __restrict__ ctx)
{
    const int b    = blockIdx.x * 8 + (threadIdx.x >> 5);
    const int lane = threadIdx.x & 31;
    const int gid  = lane >> 2;
    const int tig  = lane & 3;

    const __nv_bfloat16* Q = g_Qh + (size_t)b * HID_;
    const __nv_bfloat16* K = g_Kh + (size_t)b * HID_;

    // ---- scores: [32x32] = Q[32x64] @ K^T, 2 mtiles x 4 ntiles x 4 ktiles
    float c[2][4][4];
#pragma unroll
    for (int mt = 0; mt < 2; mt++)
#pragma unroll
        for (int nt = 0; nt < 4; nt++)
#pragma unroll
            for (int j = 0; j < 4; j++) c[mt][nt][j] = 0.0f;

#pragma unroll
    for (int kt = 0; kt < 4; kt++) {
        const int kc = kt * 16 + 2 * tig;
        uint32_t a[2][4];
#pragma unroll
        for (int mt = 0; mt < 2; mt++) {
            const int r0 = mt * 16 + gid;
            a[mt][0] = *(const uint32_t*)(Q + r0 * DH_ + kc);
            a[mt][1] = *(const uint32_t*)(Q + (r0 + 8) * DH_ + kc);
            a[mt][2] = *(const uint32_t*)(Q + r0 * DH_ + kc + 8);
            a[mt][3] = *(const uint32_t*)(Q + (r0 + 8) * DH_ + kc + 8);
        }
#pragma unroll
        for (int nt = 0; nt < 4; nt++) {
            const int n = nt * 8 + gid;
            const uint32_t b0 = *(const uint32_t*)(K + n * DH_ + kc);
            const uint32_t b1 = *(const uint32_t*)(K + n * DH_ + kc + 8);
#pragma unroll
            for (int mt = 0; mt < 2; mt++)
                mma16816(c[mt][nt], a[mt], b0, b1);
        }
    }

    // ---- softmax over n (cols), rows distributed: (mt, rh) -> row mt*16+gid+8*rh
#pragma unroll
    for (int mt = 0; mt < 2; mt++)
#pragma unroll
        for (int nt = 0; nt < 4; nt++)
#pragma unroll
            for (int j = 0; j < 4; j++) c[mt][nt][j] *= 0.125f;

#pragma unroll
    for (int mt = 0; mt < 2; mt++) {
#pragma unroll
        for (int rh = 0; rh < 2; rh++) {
            float mx = -1e30f;
#pragma unroll
            for (int nt = 0; nt < 4; nt++)
                mx = fmaxf(mx, fmaxf(c[mt][nt][2 * rh], c[mt][nt][2 * rh + 1]));
            mx = fmaxf(mx, __shfl_xor_sync(0xffffffffu, mx, 1));
            mx = fmaxf(mx, __shfl_xor_sync(0xffffffffu, mx, 2));
            float sum = 0.0f;
#pragma unroll
            for (int nt = 0; nt < 4; nt++) {
                const float e0 = __expf(c[mt][nt][2 * rh] - mx);
                const float e1 = __expf(c[mt][nt][2 * rh + 1] - mx);
                c[mt][nt][2 * rh] = e0;
                c[mt][nt][2 * rh + 1] = e1;
                sum += e0 + e1;
            }
            sum += __shfl_xor_sync(0xffffffffu, sum, 1);
            sum += __shfl_xor_sync(0xffffffffu, sum, 2);
            const float inv = 1.0f / sum;
#pragma unroll
            for (int nt = 0; nt < 4; nt++) {
                c[mt][nt][2 * rh] *= inv;
                c[mt][nt][2 * rh + 1] *= inv;
            }
        }
    }

    // ---- pack P into A-fragments (hi + lo residual)
    uint32_t ph[2][2][4], pl[2][2][4];
#pragma unroll
    for (int mt = 0; mt < 2; mt++) {
#pragma unroll
        for (int kt = 0; kt < 2; kt++) {
            const float* e = c[mt][2 * kt];      // cols kt*16 + 2tig(+1)
            const float* o = c[mt][2 * kt + 1];  // cols kt*16 + 8 + 2tig(+1)
            float h00 = __bfloat162float(__float2bfloat16_rn(e[0]));
            float h01 = __bfloat162float(__float2bfloat16_rn(e[1]));
            float h10 = __bfloat162float(__float2bfloat16_rn(e[2]));
            float h11 = __bfloat162float(__float2bfloat16_rn(e[3]));
            float g00 = __bfloat162float(__float2bfloat16_rn(o[0]));
            float g01 = __bfloat162float(__float2bfloat16_rn(o[1]));
            float g10 = __bfloat162float(__float2bfloat16_rn(o[2]));
            float g11 = __bfloat162float(__float2bfloat16_rn(o[3]));
            ph[mt][kt][0] = packbf2(h00, h01);
            ph[mt][kt][1] = packbf2(h10, h11);
            ph[mt][kt][2] = packbf2(g00, g01);
            ph[mt][kt][3] = packbf2(g10, g11);
            pl[mt][kt][0] = packbf2(e[0] - h00, e[1] - h01);
            pl[mt][kt][1] = packbf2(e[2] - h10, e[3] - h11);
            pl[mt][kt][2] = packbf2(o[0] - g00, o[1] - g01);
            pl[mt][kt][3] = packbf2(o[2] - g10, o[3] - g11);
        }
    }

    // ---- ctx = P @ Vsum : N=64 in 8 ntiles, K=32 in 2 ktiles
    float* outB = ctx + (size_t)b * HID_;
#pragma unroll
    for (int nt = 0; nt < 8; nt++) {
        const int d = nt * 8 + gid;
        float o[2][4] = {{0, 0, 0, 0}, {0, 0, 0, 0}};
#pragma unroll
        for (int kt = 0; kt < 2; kt++) {
            const int kc = kt * 16 + 2 * tig;
            const uint32_t vh0 = *(const uint32_t*)(g_VTh + d * H_ + kc);
            const uint32_t vh1 = *(const uint32_t*)(g_VTh + d * H_ + kc + 8);
            const uint32_t vl0 = *(const uint32_t*)(g_VTl + d * H_ + kc);
            const uint32_t vl1 = *(const uint32_t*)(g_VTl + d * H_ + kc + 8);
#pragma unroll
            for (int mt = 0; mt < 2; mt++) {
                mma16816(o[mt], ph[mt][kt], vh0, vh1);
                mma16816(o[mt], ph[mt][kt], vl0, vl1);
                mma16816(o[mt], pl[mt][kt], vh0, vh1);
            }
        }
#pragma unroll
        for (int mt = 0; mt < 2; mt++) {
            const int r0 = mt * 16 + gid;
            float* p0 = outB + r0 * DH_ + nt * 8 + 2 * tig;
            float* p1 = outB + (r0 + 8) * DH_ + nt * 8 + 2 * tig;
            *(float2*)p0 = float2{o[mt][0], o[mt][1]};
            *(float2*)p1 = float2{o[mt][2], o[mt][3]};
        }
    }
}

// ---------------------------------------------------------------------------
extern "C" void kernel_launch(void* const* d_in, const int* in_sizes, int n_in,
                              void* d_out, int out_size)
{
    (void)in_sizes; (void)n_in; (void)out_size;
    const int*   t   = (const int*)d_in[0];
    const float* emb = (const float*)d_in[2];
    const float* Wq  = (const float*)d_in[3];
    const float* bq  = (const float*)d_in[4];
    const float* Wk  = (const float*)d_in[5];
    const float* bk  = (const float*)d_in[6];
    const float* Wv  = (const float*)d_in[7];
    const float* bv  = (const float*)d_in[8];

    float* out = (float*)d_out;
    float* tgt = out;
    float* ctx = out + (size_t)B_ * HID_;

    static bool attr_set = false;
    if (!attr_set) {
        cudaFuncSetAttribute(qkv_mma_kernel,
                             cudaFuncAttributeMaxDynamicSharedMemorySize, SMEM_TOTAL);
        attr_set = true;
    }

    const int total4 = (B_ * E_ + 3 * HID_ * E_) / 4;
    convert_kernel<<<total4 / 256, 256>>>(t, emb, Wq, Wk, Wv);

    dim3 grid(HID_ / BN, B_ / BM, 3);
    qkv_mma_kernel<<<grid, 256, SMEM_TOTAL>>>(bq, bk, bv, tgt);

    vsum_kernel<<<8, 256>>>(tgt);
    attn_mma_kernel<<<B_ / 8, 256>>>(ctx);
}

// round 5
// speedup vs baseline: 4.8090x; 1.8214x over previous
#include <cuda_runtime.h>
#include <cuda_bf16.h>
#include <cstdint>

#define B_   4096
#define S_   10
#define H_   32
#define DH_  64
#define E_   1024
#define HID_ 2048

// GEMM tiling
#define BM 128
#define BN 128
#define BKE 32
#define STAGE_BYTES 16384
#define SMEM_TOTAL (1024 + 4 * STAGE_BYTES)

// ---------------------------------------------------------------------------
// Scratch (__device__ globals)
// ---------------------------------------------------------------------------
__device__ __nv_bfloat16 g_Qh[(size_t)B_ * HID_];
__device__ __nv_bfloat16 g_Kh[(size_t)B_ * HID_];
__device__ __nv_bfloat16 g_VTh[DH_ * H_];   // Vsum^T [d][g], hi
__device__ __nv_bfloat16 g_VTl[DH_ * H_];   // Vsum^T [d][g], lo
__device__ __nv_bfloat16 g_Ahi[(size_t)B_ * E_];
__device__ __nv_bfloat16 g_Alo[(size_t)B_ * E_];
__device__ __nv_bfloat16 g_Whi[3][(size_t)HID_ * E_];
__device__ __nv_bfloat16 g_Wvlo[(size_t)HID_ * E_];   // only Wv needs lo

// ---------------------------------------------------------------------------
// PTX helpers
// ---------------------------------------------------------------------------
__device__ __forceinline__ uint32_t s2u(const void* p) {
    return (uint32_t)__cvta_generic_to_shared(p);
}
__device__ __forceinline__ void cp16(uint32_t dst, const void* src) {
    asm volatile("cp.async.cg.shared.global [%0], [%1], 16;"
                 :: "r"(dst), "l"(__cvta_generic_to_global(src)));
}
#define CP_COMMIT() asm volatile("cp.async.commit_group;" ::: "memory")
#define CP_WAIT2()  asm volatile("cp.async.wait_group 2;" ::: "memory")

__device__ __forceinline__ void ldm4(uint32_t* r, uint32_t addr) {
    asm volatile("ldmatrix.sync.aligned.m8n8.x4.shared.b16 {%0,%1,%2,%3}, [%4];"
                 : "=r"(r[0]), "=r"(r[1]), "=r"(r[2]), "=r"(r[3]) : "r"(addr));
}
__device__ __forceinline__ void mma16816(float* d, const uint32_t* a,
                                         uint32_t b0, uint32_t b1) {
    asm volatile("mma.sync.aligned.m16n8k16.row.col.f32.bf16.bf16.f32 "
                 "{%0,%1,%2,%3}, {%4,%5,%6,%7}, {%8,%9}, {%0,%1,%2,%3};"
                 : "+f"(d[0]), "+f"(d[1]), "+f"(d[2]), "+f"(d[3])
                 : "r"(a[0]), "r"(a[1]), "r"(a[2]), "r"(a[3]),
                   "r"(b0), "r"(b1));
}
__device__ __forceinline__ uint32_t packbf2(float x, float y) {
    __nv_bfloat162 v(__float2bfloat16_rn(x), __float2bfloat16_rn(y));
    return *(uint32_t*)&v;
}

// ---------------------------------------------------------------------------
// Prep: gather emb[t]; split A into hi/lo; W -> hi (all), lo (Wv only)
// ---------------------------------------------------------------------------
__global__ __launch_bounds__(256)
void convert_kernel(const int* __restrict__ t, const float* __restrict__ emb,
                    const float* __restrict__ Wq, const float* __restrict__ Wk,
                    const float* __restrict__ Wv)
{
    const int gid = blockIdx.x * 256 + threadIdx.x;
    const int A4 = B_ * E_ / 4;
    const int W4 = HID_ * E_ / 4;
    const float* src;
    __nv_bfloat16 *dhi, *dlo = nullptr;
    size_t off;
    if (gid < A4) {
        const int b  = gid >> 8;
        const int k4 = gid & 255;
        src = emb + (size_t)t[b] * E_ + (size_t)k4 * 4;
        off = (size_t)b * E_ + (size_t)k4 * 4;
        dhi = g_Ahi; dlo = g_Alo;
    } else {
        const int j = gid - A4;
        const int w = j / W4;
        const int r = j - w * W4;
        src = (w == 0 ? Wq : (w == 1 ? Wk : Wv)) + (size_t)r * 4;
        off = (size_t)r * 4;
        dhi = g_Whi[w];
        if (w == 2) dlo = g_Wvlo;
    }
    const float4 v = *(const float4*)src;
    __nv_bfloat16 h0 = __float2bfloat16_rn(v.x);
    __nv_bfloat16 h1 = __float2bfloat16_rn(v.y);
    __nv_bfloat16 h2 = __float2bfloat16_rn(v.z);
    __nv_bfloat16 h3 = __float2bfloat16_rn(v.w);
    *(__nv_bfloat162*)(dhi + off)     = __nv_bfloat162(h0, h1);
    *(__nv_bfloat162*)(dhi + off + 2) = __nv_bfloat162(h2, h3);
    if (dlo) {
        __nv_bfloat16 l0 = __float2bfloat16_rn(v.x - __bfloat162float(h0));
        __nv_bfloat16 l1 = __float2bfloat16_rn(v.y - __bfloat162float(h1));
        __nv_bfloat16 l2 = __float2bfloat16_rn(v.z - __bfloat162float(h2));
        __nv_bfloat16 l3 = __float2bfloat16_rn(v.w - __bfloat162float(h3));
        *(__nv_bfloat162*)(dlo + off)     = __nv_bfloat162(l0, l1);
        *(__nv_bfloat162*)(dlo + off + 2) = __nv_bfloat162(l2, l3);
    }
}

// ---------------------------------------------------------------------------
// HMMA GEMM.
//   logical z=0: Q = A_hi . Wq_hi            (K'=1024, 32 chunks) -> g_Qh bf16
//   logical z=1: K = A_hi . Wk_hi            (32 chunks)          -> g_Kh bf16
//   logical z=2: V = hi.hi + hi.lo + lo.hi   (K'=3072, 96 chunks) -> outT fp32
// blockIdx.z==0 runs the heavy V pass first for tail balance.
// ---------------------------------------------------------------------------
__global__ __launch_bounds__(256, 2)
void qkv_mma_kernel(const float* __restrict__ bq, const float* __restrict__ bk,
                    const float* __restrict__ bv, float* __restrict__ outT)
{
    extern __shared__ __align__(128) char smem[];
    const int tid  = threadIdx.x;
    const int wid  = tid >> 5;
    const int lane = tid & 31;
    const int z  = (blockIdx.z == 0) ? 2 : (int)blockIdx.z - 1;
    const int m0 = blockIdx.y * BM;
    const int n0 = blockIdx.x * BN;
    const int nchunk = (z == 2) ? 96 : 32;

    const __nv_bfloat16* Whi = g_Whi[z];
    const float* bias = (z == 0) ? bq : (z == 1) ? bk : bv;

    const uint32_t sb = s2u(smem);
    float* sBias = (float*)smem;
    if (tid < BN) sBias[tid] = bias[n0 + tid];

    float acc[4][4][4];
#pragma unroll
    for (int i = 0; i < 4; i++)
#pragma unroll
        for (int j = 0; j < 4; j++)
#pragma unroll
            for (int k = 0; k < 4; k++) acc[i][j][k] = 0.0f;

    auto load_chunk = [&](int s) {
        const int ph = s >> 5;                  // 0:hi.hi 1:hi.lo 2:lo.hi
        const int k0 = (s & 31) * BKE;
        const __nv_bfloat16* Asrc = (ph == 2) ? g_Alo : g_Ahi;
        const __nv_bfloat16* Bsrc = (ph == 1) ? g_Wvlo : Whi;
        const uint32_t ab = sb + 1024 + (s & 3) * STAGE_BYTES;
        const uint32_t bb = ab + 8192;
#pragma unroll
        for (int i = 0; i < 2; i++) {
            const int idx = tid + i * 256;
            const int row = idx >> 2, kg = idx & 3;
            const uint32_t so = (uint32_t)(row * 64) +
                                (uint32_t)((kg ^ ((row >> 1) & 3)) << 4);
            cp16(ab + so, Asrc + (size_t)(m0 + row) * E_ + k0 + kg * 8);
            cp16(bb + so, Bsrc + (size_t)(n0 + row) * E_ + k0 + kg * 8);
        }
        CP_COMMIT();
    };

    load_chunk(0);
    load_chunk(1);
    load_chunk(2);

    const int m_base = (wid >> 2) * 64;
    const int n_base = (wid & 3) * 32;
    const int r    = lane & 15;
    const int half = lane >> 4;

    for (int c = 0; c < nchunk; c++) {
        CP_WAIT2();
        __syncthreads();
        if (c + 3 < nchunk) load_chunk(c + 3); else CP_COMMIT();

        const uint32_t aBase = sb + 1024 + (c & 3) * STAGE_BYTES;
        const uint32_t bBase = aBase + 8192;
#pragma unroll
        for (int kk = 0; kk < 2; kk++) {
            const int slot = kk * 2 + half;
            uint32_t Af[4][4], Bf[2][4];
#pragma unroll
            for (int mb = 0; mb < 4; mb++) {
                const int row = m_base + mb * 16 + r;
                const uint32_t addr = aBase + (uint32_t)(row * 64) +
                    (uint32_t)((slot ^ ((row >> 1) & 3)) << 4);
                ldm4(Af[mb], addr);
            }
#pragma unroll
            for (int nb2 = 0; nb2 < 2; nb2++) {
                const int row = n_base + nb2 * 16 + r;
                const uint32_t addr = bBase + (uint32_t)(row * 64) +
                    (uint32_t)((slot ^ ((row >> 1) & 3)) << 4);
                ldm4(Bf[nb2], addr);
            }
#pragma unroll
            for (int mb = 0; mb < 4; mb++)
#pragma unroll
                for (int nb = 0; nb < 4; nb++)
                    mma16816(acc[mb][nb], Af[mb],
                             Bf[nb >> 1][nb & 1], Bf[nb >> 1][(nb & 1) + 2]);
        }
    }
    __syncthreads();

    const int g   = lane >> 2;
    const int tig = lane & 3;
    if (z == 2) {
#pragma unroll
        for (int mb = 0; mb < 4; mb++) {
            const int mrow = m0 + m_base + mb * 16 + g;
#pragma unroll
            for (int nb = 0; nb < 4; nb++) {
                const int col = n_base + nb * 8 + 2 * tig;
                const float b0 = sBias[col], b1 = sBias[col + 1];
                float* d0 = outT + (size_t)mrow * HID_ + n0 + col;
                float* d1 = d0 + 8 * HID_;
                *(float2*)d0 = float2{acc[mb][nb][0] + b0, acc[mb][nb][1] + b1};
                *(float2*)d1 = float2{acc[mb][nb][2] + b0, acc[mb][nb][3] + b1};
            }
        }
    } else {
        __nv_bfloat16* Ch = (z == 0) ? g_Qh : g_Kh;
#pragma unroll
        for (int mb = 0; mb < 4; mb++) {
            const int mrow = m0 + m_base + mb * 16 + g;
#pragma unroll
            for (int nb = 0; nb < 4; nb++) {
                const int col = n_base + nb * 8 + 2 * tig;
                const float b0 = sBias[col], b1 = sBias[col + 1];
                uint32_t p0 = packbf2(acc[mb][nb][0] + b0, acc[mb][nb][1] + b1);
                uint32_t p1 = packbf2(acc[mb][nb][2] + b0, acc[mb][nb][3] + b1);
                *(uint32_t*)(Ch + (size_t)mrow * HID_ + n0 + col) = p0;
                *(uint32_t*)(Ch + (size_t)(mrow + 8) * HID_ + n0 + col) = p1;
            }
        }
    }
}

// ---------------------------------------------------------------------------
// Vsum^T: VT[d][g] = sum_{s<10} tgt[s][g*64+d], split hi/lo bf16
// ---------------------------------------------------------------------------
__global__ void vsum_kernel(const float* __restrict__ tgt)
{
    const int i = blockIdx.x * blockDim.x + threadIdx.x;
    if (i < HID_) {
        float s = 0.0f;
#pragma unroll
        for (int r = 0; r < S_; r++) s += tgt[(size_t)r * HID_ + i];
        const int g = i >> 6, d = i & 63;
        const __nv_bfloat16 hi = __float2bfloat16_rn(s);
        g_VTh[d * H_ + g] = hi;
        g_VTl[d * H_ + g] = __float2bfloat16_rn(s - __bfloat162float(hi));
    }
}

// ---------------------------------------------------------------------------
// Tensor-core attention: one warp per batch element.
// ---------------------------------------------------------------------------
__global__ __launch_bounds__(256, 1)
void attn_mma_kernel(float* __restrict__ ctx)
{
    const int b    = blockIdx.x * 8 + (threadIdx.x >> 5);
    const int lane = threadIdx.x & 31;
    const int gid  = lane >> 2;
    const int tig  = lane & 3;

    const __nv_bfloat16* Q = g_Qh + (size_t)b * HID_;
    const __nv_bfloat16* K = g_Kh + (size_t)b * HID_;

    float c[2][4][4];
#pragma unroll
    for (int mt = 0; mt < 2; mt++)
#pragma unroll
        for (int nt = 0; nt < 4; nt++)
#pragma unroll
            for (int j = 0; j < 4; j++) c[mt][nt][j] = 0.0f;

#pragma unroll
    for (int kt = 0; kt < 4; kt++) {
        const int kc = kt * 16 + 2 * tig;
        uint32_t a[2][4];
#pragma unroll
        for (int mt = 0; mt < 2; mt++) {
            const int r0 = mt * 16 + gid;
            a[mt][0] = *(const uint32_t*)(Q + r0 * DH_ + kc);
            a[mt][1] = *(const uint32_t*)(Q + (r0 + 8) * DH_ + kc);
            a[mt][2] = *(const uint32_t*)(Q + r0 * DH_ + kc + 8);
            a[mt][3] = *(const uint32_t*)(Q + (r0 + 8) * DH_ + kc + 8);
        }
#pragma unroll
        for (int nt = 0; nt < 4; nt++) {
            const int n = nt * 8 + gid;
            const uint32_t b0 = *(const uint32_t*)(K + n * DH_ + kc);
            const uint32_t b1 = *(const uint32_t*)(K + n * DH_ + kc + 8);
#pragma unroll
            for (int mt = 0; mt < 2; mt++)
                mma16816(c[mt][nt], a[mt], b0, b1);
        }
    }

#pragma unroll
    for (int mt = 0; mt < 2; mt++)
#pragma unroll
        for (int nt = 0; nt < 4; nt++)
#pragma unroll
            for (int j = 0; j < 4; j++) c[mt][nt][j] *= 0.125f;

#pragma unroll
    for (int mt = 0; mt < 2; mt++) {
#pragma unroll
        for (int rh = 0; rh < 2; rh++) {
            float mx = -1e30f;
#pragma unroll
            for (int nt = 0; nt < 4; nt++)
                mx = fmaxf(mx, fmaxf(c[mt][nt][2 * rh], c[mt][nt][2 * rh + 1]));
            mx = fmaxf(mx, __shfl_xor_sync(0xffffffffu, mx, 1));
            mx = fmaxf(mx, __shfl_xor_sync(0xffffffffu, mx, 2));
            float sum = 0.0f;
#pragma unroll
            for (int nt = 0; nt < 4; nt++) {
                const float e0 = __expf(c[mt][nt][2 * rh] - mx);
                const float e1 = __expf(c[mt][nt][2 * rh + 1] - mx);
                c[mt][nt][2 * rh] = e0;
                c[mt][nt][2 * rh + 1] = e1;
                sum += e0 + e1;
            }
            sum += __shfl_xor_sync(0xffffffffu, sum, 1);
            sum += __shfl_xor_sync(0xffffffffu, sum, 2);
            const float inv = 1.0f / sum;
#pragma unroll
            for (int nt = 0; nt < 4; nt++) {
                c[mt][nt][2 * rh] *= inv;
                c[mt][nt][2 * rh + 1] *= inv;
            }
        }
    }

    uint32_t ph[2][2][4], pl[2][2][4];
#pragma unroll
    for (int mt = 0; mt < 2; mt++) {
#pragma unroll
        for (int kt = 0; kt < 2; kt++) {
            const float* e = c[mt][2 * kt];
            const float* o = c[mt][2 * kt + 1];
            float h00 = __bfloat162float(__float2bfloat16_rn(e[0]));
            float h01 = __bfloat162float(__float2bfloat16_rn(e[1]));
            float h10 = __bfloat162float(__float2bfloat16_rn(e[2]));
            float h11 = __bfloat162float(__float2bfloat16_rn(e[3]));
            float g00 = __bfloat162float(__float2bfloat16_rn(o[0]));
            float g01 = __bfloat162float(__float2bfloat16_rn(o[1]));
            float g10 = __bfloat162float(__float2bfloat16_rn(o[2]));
            float g11 = __bfloat162float(__float2bfloat16_rn(o[3]));
            ph[mt][kt][0] = packbf2(h00, h01);
            ph[mt][kt][1] = packbf2(h10, h11);
            ph[mt][kt][2] = packbf2(g00, g01);
            ph[mt][kt][3] = packbf2(g10, g11);
            pl[mt][kt][0] = packbf2(e[0] - h00, e[1] - h01);
            pl[mt][kt][1] = packbf2(e[2] - h10, e[3] - h11);
            pl[mt][kt][2] = packbf2(o[0] - g00, o[1] - g01);
            pl[mt][kt][3] = packbf2(o[2] - g10, o[3] - g11);
        }
    }

    float* outB = ctx + (size_t)b * HID_;
#pragma unroll
    for (int nt = 0; nt < 8; nt++) {
        const int d = nt * 8 + gid;
        float o[2][4] = {{0, 0, 0, 0}, {0, 0, 0, 0}};
#pragma unroll
        for (int kt = 0; kt < 2; kt++) {
            const int kc = kt * 16 + 2 * tig;
            const uint32_t vh0 = *(const uint32_t*)(g_VTh + d * H_ + kc);
            const uint32_t vh1 = *(const uint32_t*)(g_VTh + d * H_ + kc + 8);
            const uint32_t vl0 = *(const uint32_t*)(g_VTl + d * H_ + kc);
            const uint32_t vl1 = *(const uint32_t*)(g_VTl + d * H_ + kc + 8);
#pragma unroll
            for (int mt = 0; mt < 2; mt++) {
                mma16816(o[mt], ph[mt][kt], vh0, vh1);
                mma16816(o[mt], ph[mt][kt], vl0, vl1);
                mma16816(o[mt], pl[mt][kt], vh0, vh1);
            }
        }
#pragma unroll
        for (int mt = 0; mt < 2; mt++) {
            const int r0 = mt * 16 + gid;
            float* p0 = outB + r0 * DH_ + nt * 8 + 2 * tig;
            float* p1 = outB + (r0 + 8) * DH_ + nt * 8 + 2 * tig;
            *(float2*)p0 = float2{o[mt][0], o[mt][1]};
            *(float2*)p1 = float2{o[mt][2], o[mt][3]};
        }
    }
}

// ---------------------------------------------------------------------------
extern "C" void kernel_launch(void* const* d_in, const int* in_sizes, int n_in,
                              void* d_out, int out_size)
{
    (void)in_sizes; (void)n_in; (void)out_size;
    const int*   t   = (const int*)d_in[0];
    const float* emb = (const float*)d_in[2];
    const float* Wq  = (const float*)d_in[3];
    const float* bq  = (const float*)d_in[4];
    const float* Wk  = (const float*)d_in[5];
    const float* bk  = (const float*)d_in[6];
    const float* Wv  = (const float*)d_in[7];
    const float* bv  = (const float*)d_in[8];

    float* out = (float*)d_out;
    float* tgt = out;
    float* ctx = out + (size_t)B_ * HID_;

    static bool attr_set = false;
    if (!attr_set) {
        cudaFuncSetAttribute(qkv_mma_kernel,
                             cudaFuncAttributeMaxDynamicSharedMemorySize, SMEM_TOTAL);
        attr_set = true;
    }

    const int total4 = (B_ * E_ + 3 * HID_ * E_) / 4;
    convert_kernel<<<total4 / 256, 256>>>(t, emb, Wq, Wk, Wv);

    dim3 grid(HID_ / BN, B_ / BM, 3);
    qkv_mma_kernel<<<grid, 256, SMEM_TOTAL>>>(bq, bk, bv, tgt);

    vsum_kernel<<<8, 256>>>(tgt);
    attn_mma_kernel<<<B_ / 8, 256>>>(ctx);
}

// round 6
// speedup vs baseline: 5.0657x; 1.0534x over previous
#include <cuda_runtime.h>
#include <cuda_bf16.h>
#include <cstdint>

#define B_   4096
#define S_   10
#define H_   32
#define DH_  64
#define E_   1024
#define HID_ 2048

// GEMM tiling: 128x128 CTA tile, K-chunk = 64 bf16 (128 B rows), 3 stages
#define BM 128
#define BN 128
#define BKE 64
#define STAGE_BYTES 32768          // (128 rows * 128 B) * 2 operands
#define SMEM_TOTAL (1024 + 3 * STAGE_BYTES)

#define ATTN_SMEM 65536            // 8 batches * (Q 4KB + K 4KB)

// ---------------------------------------------------------------------------
// Scratch (__device__ globals)
// ---------------------------------------------------------------------------
__device__ __nv_bfloat16 g_Qh[(size_t)B_ * HID_];
__device__ __nv_bfloat16 g_Kh[(size_t)B_ * HID_];
__device__ __nv_bfloat16 g_VTh[DH_ * H_];
__device__ __nv_bfloat16 g_VTl[DH_ * H_];
__device__ __nv_bfloat16 g_Ahi[(size_t)B_ * E_];
__device__ __nv_bfloat16 g_Alo[(size_t)B_ * E_];
__device__ __nv_bfloat16 g_Whi[3][(size_t)HID_ * E_];
__device__ __nv_bfloat16 g_Wvlo[(size_t)HID_ * E_];

// ---------------------------------------------------------------------------
// PTX helpers
// ---------------------------------------------------------------------------
__device__ __forceinline__ uint32_t s2u(const void* p) {
    return (uint32_t)__cvta_generic_to_shared(p);
}
__device__ __forceinline__ void cp16(uint32_t dst, const void* src) {
    asm volatile("cp.async.cg.shared.global [%0], [%1], 16;"
                 :: "r"(dst), "l"(__cvta_generic_to_global(src)));
}
#define CP_COMMIT() asm volatile("cp.async.commit_group;" ::: "memory")
#define CP_WAIT1()  asm volatile("cp.async.wait_group 1;" ::: "memory")
#define CP_WAIT0()  asm volatile("cp.async.wait_group 0;" ::: "memory")

__device__ __forceinline__ void ldm4(uint32_t* r, uint32_t addr) {
    asm volatile("ldmatrix.sync.aligned.m8n8.x4.shared.b16 {%0,%1,%2,%3}, [%4];"
                 : "=r"(r[0]), "=r"(r[1]), "=r"(r[2]), "=r"(r[3]) : "r"(addr));
}
__device__ __forceinline__ void mma16816(float* d, const uint32_t* a,
                                         uint32_t b0, uint32_t b1) {
    asm volatile("mma.sync.aligned.m16n8k16.row.col.f32.bf16.bf16.f32 "
                 "{%0,%1,%2,%3}, {%4,%5,%6,%7}, {%8,%9}, {%0,%1,%2,%3};"
                 : "+f"(d[0]), "+f"(d[1]), "+f"(d[2]), "+f"(d[3])
                 : "r"(a[0]), "r"(a[1]), "r"(a[2]), "r"(a[3]),
                   "r"(b0), "r"(b1));
}
__device__ __forceinline__ uint32_t packbf2(float x, float y) {
    __nv_bfloat162 v(__float2bfloat16_rn(x), __float2bfloat16_rn(y));
    return *(uint32_t*)&v;
}
// canonical SW128 swizzle of a byte offset within a 128B-row tile
__device__ __forceinline__ uint32_t sw128(uint32_t off) {
    return off ^ ((off >> 3) & 0x70);
}

// ---------------------------------------------------------------------------
// Prep: gather emb[t]; split A into hi/lo; W -> hi (all), lo (Wv only)
// ---------------------------------------------------------------------------
__global__ __launch_bounds__(256)
void convert_kernel(const int* __restrict__ t, const float* __restrict__ emb,
                    const float* __restrict__ Wq, const float* __restrict__ Wk,
                    const float* __restrict__ Wv)
{
    const int gid = blockIdx.x * 256 + threadIdx.x;
    const int A4 = B_ * E_ / 4;
    const int W4 = HID_ * E_ / 4;
    const float* src;
    __nv_bfloat16 *dhi, *dlo = nullptr;
    size_t off;
    if (gid < A4) {
        const int b  = gid >> 8;
        const int k4 = gid & 255;
        src = emb + (size_t)t[b] * E_ + (size_t)k4 * 4;
        off = (size_t)b * E_ + (size_t)k4 * 4;
        dhi = g_Ahi; dlo = g_Alo;
    } else {
        const int j = gid - A4;
        const int w = j / W4;
        const int r = j - w * W4;
        src = (w == 0 ? Wq : (w == 1 ? Wk : Wv)) + (size_t)r * 4;
        off = (size_t)r * 4;
        dhi = g_Whi[w];
        if (w == 2) dlo = g_Wvlo;
    }
    const float4 v = *(const float4*)src;
    __nv_bfloat16 h0 = __float2bfloat16_rn(v.x);
    __nv_bfloat16 h1 = __float2bfloat16_rn(v.y);
    __nv_bfloat16 h2 = __float2bfloat16_rn(v.z);
    __nv_bfloat16 h3 = __float2bfloat16_rn(v.w);
    *(__nv_bfloat162*)(dhi + off)     = __nv_bfloat162(h0, h1);
    *(__nv_bfloat162*)(dhi + off + 2) = __nv_bfloat162(h2, h3);
    if (dlo) {
        __nv_bfloat16 l0 = __float2bfloat16_rn(v.x - __bfloat162float(h0));
        __nv_bfloat16 l1 = __float2bfloat16_rn(v.y - __bfloat162float(h1));
        __nv_bfloat16 l2 = __float2bfloat16_rn(v.z - __bfloat162float(h2));
        __nv_bfloat16 l3 = __float2bfloat16_rn(v.w - __bfloat162float(h3));
        *(__nv_bfloat162*)(dlo + off)     = __nv_bfloat162(l0, l1);
        *(__nv_bfloat162*)(dlo + off + 2) = __nv_bfloat162(l2, l3);
    }
}

// ---------------------------------------------------------------------------
// HMMA GEMM.
//   z=0: Q = A_hi . Wq_hi            (16 chunks) -> g_Qh bf16
//   z=1: K = A_hi . Wk_hi            (16 chunks) -> g_Kh bf16
//   z=2: V = hi.hi + hi.lo + lo.hi   (48 chunks) -> outT fp32
// blockIdx.z==0 runs the heavy V pass first for tail balance.
// ---------------------------------------------------------------------------
__global__ __launch_bounds__(256, 2)
void qkv_mma_kernel(const float* __restrict__ bq, const float* __restrict__ bk,
                    const float* __restrict__ bv, float* __restrict__ outT)
{
    extern __shared__ __align__(128) char smem[];
    const int tid  = threadIdx.x;
    const int wid  = tid >> 5;
    const int lane = tid & 31;
    const int z  = (blockIdx.z == 0) ? 2 : (int)blockIdx.z - 1;
    const int m0 = blockIdx.y * BM;
    const int n0 = blockIdx.x * BN;
    const int nchunk = (z == 2) ? 48 : 16;

    const __nv_bfloat16* Whi = g_Whi[z];
    const float* bias = (z == 0) ? bq : (z == 1) ? bk : bv;

    const uint32_t sb = s2u(smem);
    float* sBias = (float*)smem;
    if (tid < BN) sBias[tid] = bias[n0 + tid];

    float acc[4][4][4];
#pragma unroll
    for (int i = 0; i < 4; i++)
#pragma unroll
        for (int j = 0; j < 4; j++)
#pragma unroll
            for (int k = 0; k < 4; k++) acc[i][j][k] = 0.0f;

    auto load_chunk = [&](int s) {
        const int ph = s >> 4;                  // 0:hi.hi 1:hi.lo 2:lo.hi
        const int k0 = (s & 15) * BKE;
        const __nv_bfloat16* Asrc = (ph == 2) ? g_Alo : g_Ahi;
        const __nv_bfloat16* Bsrc = (ph == 1) ? g_Wvlo : Whi;
        const uint32_t ab = sb + 1024 + (s % 3) * STAGE_BYTES;
        const uint32_t bb = ab + 16384;
#pragma unroll
        for (int i = 0; i < 4; i++) {
            const int idx = tid + i * 256;
            const int row = idx >> 3, kg = idx & 7;
            const uint32_t so = sw128((uint32_t)(row * 128 + kg * 16));
            cp16(ab + so, Asrc + (size_t)(m0 + row) * E_ + k0 + kg * 8);
            cp16(bb + so, Bsrc + (size_t)(n0 + row) * E_ + k0 + kg * 8);
        }
        CP_COMMIT();
    };

    load_chunk(0);
    load_chunk(1);

    const int m_base = (wid >> 2) * 64;
    const int n_base = (wid & 3) * 32;
    const int r    = lane & 15;
    const int half = lane >> 4;

    for (int c = 0; c < nchunk; c++) {
        CP_WAIT1();
        __syncthreads();
        if (c + 2 < nchunk) load_chunk(c + 2); else CP_COMMIT();

        const uint32_t aBase = sb + 1024 + (c % 3) * STAGE_BYTES;
        const uint32_t bBase = aBase + 16384;
#pragma unroll
        for (int kk = 0; kk < 4; kk++) {
            const int slot = kk * 2 + half;
            uint32_t Af[4][4], Bf[2][4];
#pragma unroll
            for (int mb = 0; mb < 4; mb++) {
                const int row = m_base + mb * 16 + r;
                const uint32_t addr = aBase +
                    sw128((uint32_t)(row * 128 + slot * 16));
                ldm4(Af[mb], addr);
            }
#pragma unroll
            for (int nb2 = 0; nb2 < 2; nb2++) {
                const int row = n_base + nb2 * 16 + r;
                const uint32_t addr = bBase +
                    sw128((uint32_t)(row * 128 + slot * 16));
                ldm4(Bf[nb2], addr);
            }
#pragma unroll
            for (int mb = 0; mb < 4; mb++)
#pragma unroll
                for (int nb = 0; nb < 4; nb++)
                    mma16816(acc[mb][nb], Af[mb],
                             Bf[nb >> 1][nb & 1], Bf[nb >> 1][(nb & 1) + 2]);
        }
    }
    __syncthreads();

    const int g   = lane >> 2;
    const int tig = lane & 3;
    if (z == 2) {
#pragma unroll
        for (int mb = 0; mb < 4; mb++) {
            const int mrow = m0 + m_base + mb * 16 + g;
#pragma unroll
            for (int nb = 0; nb < 4; nb++) {
                const int col = n_base + nb * 8 + 2 * tig;
                const float b0 = sBias[col], b1 = sBias[col + 1];
                float* d0 = outT + (size_t)mrow * HID_ + n0 + col;
                float* d1 = d0 + 8 * HID_;
                *(float2*)d0 = float2{acc[mb][nb][0] + b0, acc[mb][nb][1] + b1};
                *(float2*)d1 = float2{acc[mb][nb][2] + b0, acc[mb][nb][3] + b1};
            }
        }
    } else {
        __nv_bfloat16* Ch = (z == 0) ? g_Qh : g_Kh;
#pragma unroll
        for (int mb = 0; mb < 4; mb++) {
            const int mrow = m0 + m_base + mb * 16 + g;
#pragma unroll
            for (int nb = 0; nb < 4; nb++) {
                const int col = n_base + nb * 8 + 2 * tig;
                const float b0 = sBias[col], b1 = sBias[col + 1];
                uint32_t p0 = packbf2(acc[mb][nb][0] + b0, acc[mb][nb][1] + b1);
                uint32_t p1 = packbf2(acc[mb][nb][2] + b0, acc[mb][nb][3] + b1);
                *(uint32_t*)(Ch + (size_t)mrow * HID_ + n0 + col) = p0;
                *(uint32_t*)(Ch + (size_t)(mrow + 8) * HID_ + n0 + col) = p1;
            }
        }
    }
}

// ---------------------------------------------------------------------------
// Vsum^T: VT[d][g] = sum_{s<10} tgt[s][g*64+d], split hi/lo bf16
// ---------------------------------------------------------------------------
__global__ void vsum_kernel(const float* __restrict__ tgt)
{
    const int i = blockIdx.x * blockDim.x + threadIdx.x;
    if (i < HID_) {
        float s = 0.0f;
#pragma unroll
        for (int r = 0; r < S_; r++) s += tgt[(size_t)r * HID_ + i];
        const int g = i >> 6, d = i & 63;
        const __nv_bfloat16 hi = __float2bfloat16_rn(s);
        g_VTh[d * H_ + g] = hi;
        g_VTl[d * H_ + g] = __float2bfloat16_rn(s - __bfloat162float(hi));
    }
}

// ---------------------------------------------------------------------------
// Tensor-core attention: warp = batch; Q/K staged in smem via cp.async,
// fragments via ldmatrix. Softmax in-fragment; PV with hi/lo split.
// ---------------------------------------------------------------------------
__global__ __launch_bounds__(256, 1)
void attn_mma_kernel(float* __restrict__ ctx)
{
    extern __shared__ __align__(128) char smem[];
    const int tid  = threadIdx.x;
    const int w    = tid >> 5;
    const int lane = tid & 31;
    const int gid  = lane >> 2;
    const int tig  = lane & 3;
    const int b0   = blockIdx.x * 8;
    const uint32_t sb = s2u(smem);

    // stage Q,K for 8 batches: batch w -> Q at w*8192, K at w*8192+4096
#pragma unroll
    for (int i = 0; i < 16; i++) {
        const int idx  = tid + i * 256;          // 0..4095
        const int bat  = idx >> 9;
        const int r9   = idx & 511;
        const int isK  = r9 >> 8;
        const int row  = (r9 >> 3) & 31;
        const int slot = r9 & 7;
        const __nv_bfloat16* src =
            (isK ? g_Kh : g_Qh) + (size_t)(b0 + bat) * HID_ + row * 64 + slot * 8;
        const uint32_t dst = sb + bat * 8192 + isK * 4096 +
            sw128((uint32_t)(row * 128 + slot * 16));
        cp16(dst, src);
    }
    CP_COMMIT();
    CP_WAIT0();
    __syncthreads();

    const uint32_t sQ = sb + w * 8192;
    const uint32_t sK = sQ + 4096;
    const int r    = lane & 15;
    const int half = lane >> 4;

    // ---- scores: [32x32] = Q @ K^T
    float c[2][4][4];
#pragma unroll
    for (int mt = 0; mt < 2; mt++)
#pragma unroll
        for (int nt = 0; nt < 4; nt++)
#pragma unroll
            for (int j = 0; j < 4; j++) c[mt][nt][j] = 0.0f;

#pragma unroll
    for (int kt = 0; kt < 4; kt++) {
        const int slot = kt * 2 + half;
        uint32_t a[2][4], Bf[2][4];
#pragma unroll
        for (int mt = 0; mt < 2; mt++) {
            const int row = mt * 16 + r;
            ldm4(a[mt], sQ + sw128((uint32_t)(row * 128 + slot * 16)));
        }
#pragma unroll
        for (int nt2 = 0; nt2 < 2; nt2++) {
            const int row = nt2 * 16 + r;
            ldm4(Bf[nt2], sK + sw128((uint32_t)(row * 128 + slot * 16)));
        }
#pragma unroll
        for (int mt = 0; mt < 2; mt++)
#pragma unroll
            for (int nt = 0; nt < 4; nt++)
                mma16816(c[mt][nt], a[mt],
                         Bf[nt >> 1][nt & 1], Bf[nt >> 1][(nt & 1) + 2]);
    }

    // ---- softmax over cols
#pragma unroll
    for (int mt = 0; mt < 2; mt++)
#pragma unroll
        for (int nt = 0; nt < 4; nt++)
#pragma unroll
            for (int j = 0; j < 4; j++) c[mt][nt][j] *= 0.125f;

#pragma unroll
    for (int mt = 0; mt < 2; mt++) {
#pragma unroll
        for (int rh = 0; rh < 2; rh++) {
            float mx = -1e30f;
#pragma unroll
            for (int nt = 0; nt < 4; nt++)
                mx = fmaxf(mx, fmaxf(c[mt][nt][2 * rh], c[mt][nt][2 * rh + 1]));
            mx = fmaxf(mx, __shfl_xor_sync(0xffffffffu, mx, 1));
            mx = fmaxf(mx, __shfl_xor_sync(0xffffffffu, mx, 2));
            float sum = 0.0f;
#pragma unroll
            for (int nt = 0; nt < 4; nt++) {
                const float e0 = __expf(c[mt][nt][2 * rh] - mx);
                const float e1 = __expf(c[mt][nt][2 * rh + 1] - mx);
                c[mt][nt][2 * rh] = e0;
                c[mt][nt][2 * rh + 1] = e1;
                sum += e0 + e1;
            }
            sum += __shfl_xor_sync(0xffffffffu, sum, 1);
            sum += __shfl_xor_sync(0xffffffffu, sum, 2);
            const float inv = 1.0f / sum;
#pragma unroll
            for (int nt = 0; nt < 4; nt++) {
                c[mt][nt][2 * rh] *= inv;
                c[mt][nt][2 * rh + 1] *= inv;
            }
        }
    }

    // ---- pack P (hi + lo residual) into A-fragments
    uint32_t ph[2][2][4], pl[2][2][4];
#pragma unroll
    for (int mt = 0; mt < 2; mt++) {
#pragma unroll
        for (int kt = 0; kt < 2; kt++) {
            const float* e = c[mt][2 * kt];
            const float* o = c[mt][2 * kt + 1];
            float h00 = __bfloat162float(__float2bfloat16_rn(e[0]));
            float h01 = __bfloat162float(__float2bfloat16_rn(e[1]));
            float h10 = __bfloat162float(__float2bfloat16_rn(e[2]));
            float h11 = __bfloat162float(__float2bfloat16_rn(e[3]));
            float g00 = __bfloat162float(__float2bfloat16_rn(o[0]));
            float g01 = __bfloat162float(__float2bfloat16_rn(o[1]));
            float g10 = __bfloat162float(__float2bfloat16_rn(o[2]));
            float g11 = __bfloat162float(__float2bfloat16_rn(o[3]));
            ph[mt][kt][0] = packbf2(h00, h01);
            ph[mt][kt][1] = packbf2(h10, h11);
            ph[mt][kt][2] = packbf2(g00, g01);
            ph[mt][kt][3] = packbf2(g10, g11);
            pl[mt][kt][0] = packbf2(e[0] - h00, e[1] - h01);
            pl[mt][kt][1] = packbf2(e[2] - h10, e[3] - h11);
            pl[mt][kt][2] = packbf2(o[0] - g00, o[1] - g01);
            pl[mt][kt][3] = packbf2(o[2] - g10, o[3] - g11);
        }
    }

    // ---- ctx = P @ Vsum
    float* outB = ctx + (size_t)(b0 + w) * HID_;
#pragma unroll
    for (int nt = 0; nt < 8; nt++) {
        const int d = nt * 8 + gid;
        float o[2][4] = {{0, 0, 0, 0}, {0, 0, 0, 0}};
#pragma unroll
        for (int kt = 0; kt < 2; kt++) {
            const int kc = kt * 16 + 2 * tig;
            const uint32_t vh0 = *(const uint32_t*)(g_VTh + d * H_ + kc);
            const uint32_t vh1 = *(const uint32_t*)(g_VTh + d * H_ + kc + 8);
            const uint32_t vl0 = *(const uint32_t*)(g_VTl + d * H_ + kc);
            const uint32_t vl1 = *(const uint32_t*)(g_VTl + d * H_ + kc + 8);
#pragma unroll
            for (int mt = 0; mt < 2; mt++) {
                mma16816(o[mt], ph[mt][kt], vh0, vh1);
                mma16816(o[mt], ph[mt][kt], vl0, vl1);
                mma16816(o[mt], pl[mt][kt], vh0, vh1);
            }
        }
#pragma unroll
        for (int mt = 0; mt < 2; mt++) {
            const int r0 = mt * 16 + gid;
            float* p0 = outB + r0 * DH_ + nt * 8 + 2 * tig;
            float* p1 = outB + (r0 + 8) * DH_ + nt * 8 + 2 * tig;
            *(float2*)p0 = float2{o[mt][0], o[mt][1]};
            *(float2*)p1 = float2{o[mt][2], o[mt][3]};
        }
    }
}

// ---------------------------------------------------------------------------
extern "C" void kernel_launch(void* const* d_in, const int* in_sizes, int n_in,
                              void* d_out, int out_size)
{
    (void)in_sizes; (void)n_in; (void)out_size;
    const int*   t   = (const int*)d_in[0];
    const float* emb = (const float*)d_in[2];
    const float* Wq  = (const float*)d_in[3];
    const float* bq  = (const float*)d_in[4];
    const float* Wk  = (const float*)d_in[5];
    const float* bk  = (const float*)d_in[6];
    const float* Wv  = (const float*)d_in[7];
    const float* bv  = (const float*)d_in[8];

    float* out = (float*)d_out;
    float* tgt = out;
    float* ctx = out + (size_t)B_ * HID_;

    static bool attr_set = false;
    if (!attr_set) {
        cudaFuncSetAttribute(qkv_mma_kernel,
                             cudaFuncAttributeMaxDynamicSharedMemorySize, SMEM_TOTAL);
        cudaFuncSetAttribute(attn_mma_kernel,
                             cudaFuncAttributeMaxDynamicSharedMemorySize, ATTN_SMEM);
        attr_set = true;
    }

    const int total4 = (B_ * E_ + 3 * HID_ * E_) / 4;
    convert_kernel<<<total4 / 256, 256>>>(t, emb, Wq, Wk, Wv);

    dim3 grid(HID_ / BN, B_ / BM, 3);
    qkv_mma_kernel<<<grid, 256, SMEM_TOTAL>>>(bq, bk, bv, tgt);

    vsum_kernel<<<8, 256>>>(tgt);
    attn_mma_kernel<<<B_ / 8, 256, ATTN_SMEM>>>(ctx);
}